// round 14
// baseline (speedup 1.0000x reference)
#include <cuda_runtime.h>
#include <cstdint>

#define BB 32
#define KK 10
#define NN 128
#define FF 512
#define NITER 30
#define LRc 0.5f
#define RHOc 10.0f
#define LOG2E 1.4426950408889634f

typedef unsigned long long u64;

// ---- scratch (static device globals: allocation-free) ----
static __device__ float g_Gp[8][BB * NN * NN];   // 16 MB: eight K-eighths of X X^T
static __device__ float g_C[BB * NN * NN];       // 2 MB cost matrix

__device__ __forceinline__ float wsum(float v) {
#pragma unroll
    for (int o = 16; o; o >>= 1) v += __shfl_xor_sync(0xffffffffu, v, o);
    return v;
}
__device__ __forceinline__ float hsum16(float v) {
#pragma unroll
    for (int o = 8; o; o >>= 1) v += __shfl_xor_sync(0xffffffffu, v, o);
    return v;
}
__device__ __forceinline__ float hmax16(float v) {
#pragma unroll
    for (int o = 8; o; o >>= 1) v = fmaxf(v, __shfl_xor_sync(0xffffffffu, v, o));
    return v;
}
__device__ __forceinline__ float ex2(float x) {
    float r;
    asm("ex2.approx.f32 %0, %1;" : "=f"(r) : "f"(x));
    return r;
}
__device__ __forceinline__ float rcpa(float x) {
    float r;
    asm("rcp.approx.f32 %0, %1;" : "=f"(r) : "f"(x));
    return r;
}
// ---- packed f32x2 ----
__device__ __forceinline__ u64 pk(float lo, float hi) {
    u64 r;
    asm("mov.b64 %0, {%1, %2};" : "=l"(r) : "f"(lo), "f"(hi));
    return r;
}
__device__ __forceinline__ void upk(float& lo, float& hi, u64 v) {
    asm("mov.b64 {%0, %1}, %2;" : "=f"(lo), "=f"(hi) : "l"(v));
}
__device__ __forceinline__ u64 fma2(u64 a, u64 b, u64 c) {
    u64 d;
    asm("fma.rn.f32x2 %0, %1, %2, %3;" : "=l"(d) : "l"(a), "l"(b), "l"(c));
    return d;
}
__device__ __forceinline__ u64 mul2(u64 a, u64 b) {
    u64 d;
    asm("mul.rn.f32x2 %0, %1, %2;" : "=l"(d) : "l"(a), "l"(b));
    return d;
}
__device__ __forceinline__ u64 add2(u64 a, u64 b) {
    u64 d;
    asm("add.rn.f32x2 %0, %1, %2;" : "=l"(d) : "l"(a), "l"(b));
    return d;
}
__device__ __forceinline__ uint32_t smem_u32(const void* p) {
    uint32_t a;
    asm("{ .reg .u64 t; cvta.to.shared.u64 t, %1; cvt.u32.u64 %0, t; }"
        : "=r"(a) : "l"(p));
    return a;
}
// mapa is a pure address translation -> non-volatile (hoistable/CSE-able)
__device__ __forceinline__ float dsmem_ld(uint32_t addr, uint32_t rank) {
    uint32_t ra; float v;
    asm("mapa.shared::cluster.u32 %0, %1, %2;" : "=r"(ra) : "r"(addr), "r"(rank));
    asm volatile("ld.shared::cluster.f32 %0, [%1];" : "=f"(v) : "r"(ra));
    return v;
}
__device__ __forceinline__ void dsmem_ld2(float& a, float& b, uint32_t addr, uint32_t rank) {
    uint32_t ra;
    asm("mapa.shared::cluster.u32 %0, %1, %2;" : "=r"(ra) : "r"(addr), "r"(rank));
    asm volatile("ld.shared::cluster.v2.f32 {%0, %1}, [%2];" : "=f"(a), "=f"(b) : "r"(ra));
}
__device__ __forceinline__ void mbar_init(uint32_t mbar, uint32_t count) {
    asm volatile("mbarrier.init.shared.b64 [%0], %1;" :: "r"(mbar), "r"(count) : "memory");
}
__device__ __forceinline__ void mbar_arrive_rank(uint32_t mbar, uint32_t rank) {
    asm volatile(
        "{ .reg .b32 ra; mapa.shared::cluster.u32 ra, %0, %1;\n\t"
        "mbarrier.arrive.release.cluster.shared::cluster.b64 _, [ra]; }"
        :: "r"(mbar), "r"(rank) : "memory");
}
__device__ __forceinline__ void mbar_wait(uint32_t mbar, uint32_t parity) {
    asm volatile(
        "{ .reg .pred P;\n\t"
        "WL_%=:\n\t"
        "mbarrier.try_wait.parity.acquire.cluster.shared::cta.b64 P, [%0], %1, 0x989680;\n\t"
        "@P bra.uni WD_%=;\n\t"
        "bra.uni WL_%=;\n\t"
        "WD_%=: }"
        :: "r"(mbar), "r"(parity) : "memory");
}
#define CLUSTER_SYNC() do { \
    asm volatile("barrier.cluster.arrive.aligned;" ::: "memory"); \
    asm volatile("barrier.cluster.wait.aligned;" ::: "memory"); } while (0)

// ===== prologue A: G = X X^T, 128x128 tile per (b, K-eighth) — 256 CTAs =====
__global__ void __launch_bounds__(256) proA_kernel(const float* __restrict__ X) {
    int b = blockIdx.x >> 3, ks = blockIdx.x & 7;
    __shared__ float As[16][NN];      // 8 KB; A tile == B tile (G = X X^T)
    const float* Xb = X + (size_t)b * NN * FF;
    int t = threadIdx.x;
    int tx = t & 15, ty = t >> 4;
    int row = t & 127, cq = t >> 7;   // loader mapping
    float acc[8][8];
#pragma unroll
    for (int i = 0; i < 8; i++)
#pragma unroll
        for (int j = 0; j < 8; j++) acc[i][j] = 0.f;

    for (int kc = ks * 64; kc < ks * 64 + 64; kc += 16) {
        float4 v0 = *(const float4*)(Xb + (size_t)row * FF + kc + cq * 8);
        float4 v1 = *(const float4*)(Xb + (size_t)row * FF + kc + cq * 8 + 4);
        if (kc != ks * 64) __syncthreads();
        As[cq * 8 + 0][row] = v0.x; As[cq * 8 + 1][row] = v0.y;
        As[cq * 8 + 2][row] = v0.z; As[cq * 8 + 3][row] = v0.w;
        As[cq * 8 + 4][row] = v1.x; As[cq * 8 + 5][row] = v1.y;
        As[cq * 8 + 6][row] = v1.z; As[cq * 8 + 7][row] = v1.w;
        __syncthreads();
#pragma unroll
        for (int kk = 0; kk < 16; kk++) {
            float4 a0 = *(const float4*)&As[kk][ty * 8];
            float4 a1 = *(const float4*)&As[kk][ty * 8 + 4];
            float4 b0 = *(const float4*)&As[kk][tx * 8];
            float4 b1 = *(const float4*)&As[kk][tx * 8 + 4];
            float av[8] = {a0.x, a0.y, a0.z, a0.w, a1.x, a1.y, a1.z, a1.w};
            float bv[8] = {b0.x, b0.y, b0.z, b0.w, b1.x, b1.y, b1.z, b1.w};
#pragma unroll
            for (int i = 0; i < 8; i++)
#pragma unroll
                for (int j = 0; j < 8; j++)
                    acc[i][j] = fmaf(av[i], bv[j], acc[i][j]);
        }
    }
#pragma unroll
    for (int i = 0; i < 8; i++) {
        float* orow = g_Gp[ks] + ((size_t)b * NN + ty * 8 + i) * NN + tx * 8;
        *(float4*)orow       = make_float4(acc[i][0], acc[i][1], acc[i][2], acc[i][3]);
        *(float4*)(orow + 4) = make_float4(acc[i][4], acc[i][5], acc[i][6], acc[i][7]);
    }
}

// ===== persistent cluster solver: phase-0 C build + 30 iterations =====
#define SM_S     0
#define SM_W     16384   /* 128 */
#define SM_QLQ   16512   /* 512: float4 (q,q,lq,lq) per row; 16B aligned */
#define SM_PW    17024   /* 1024 warp partials; phase0: xns in [0..127] */
#define SM_PB    18048   /* 256 double-buffered p row */
#define SM_CROW  18304   /* 128 crow slice (phase 0 exchange) */
#define SM_CST   18432   /* 8 */
#define SM_A     18440   /* 1 */
#define SM_MBAR  18442   /* 16B, 8-aligned (18442*4 % 8 == 0) */
#define SM_FLOATS 18446
#define SMEM_BYTES (SM_FLOATS * 4)

__global__ void __cluster_dims__(KK, 1, 1) __launch_bounds__(256, 3)
solve_kernel(const float* __restrict__ Q, const float* __restrict__ theta,
             float* __restrict__ p_out) {
    extern __shared__ float sm[];
    float* S    = sm + SM_S;
    float* w_s  = sm + SM_W;
    float* qlq  = sm + SM_QLQ;
    float* p_w  = sm + SM_PW;
    float* pb   = sm + SM_PB;
    float* crow = sm + SM_CROW;
    float* cst  = sm + SM_CST;

    int k = blockIdx.x, b = blockIdx.y;
    int bk = b * KK + k;
    int tid = threadIdx.x;
    int warp = tid >> 5, lane = tid & 31;
    int h = lane >> 4, hl = lane & 15;
    int j0 = hl * 4, j1 = 64 + hl * 4;
    int r0 = tid % KK;                       // scalar rotation for crow gather only

    const float* Cb = g_C + (size_t)b * NN * NN;
    uint32_t pb_u32 = smem_u32(pb);
    uint32_t crow_u32 = smem_u32(crow);
    uint32_t mbar_u32 = smem_u32(sm + SM_MBAR);
    float th = theta[bk];

    // ---------- phase 0: init smem, build C rows, a0 ----------
    if (tid < NN) {
        float ql = Q[bk * NN + tid];
        float lq = (LRc * LOG2E) * ql;
        *(float4*)&qlq[4 * tid] = make_float4(ql, ql, lq, lq);
        w_s[tid] = 0.f;                      // iter 0: constant w cancels
        // xn_j == G_jj (diag of full Gram); dgv == 0 exactly -> dropped
        float dg = 0.f;
#pragma unroll
        for (int pp = 0; pp < 8; pp++)
            dg += g_Gp[pp][((size_t)b * NN + tid) * NN + tid];
        p_w[tid] = dg;
    }
    {   // S preinit to 1/128
        float4 u4 = make_float4(0.0078125f, 0.0078125f, 0.0078125f, 0.0078125f);
        for (int i = tid; i < NN * NN / 4; i += 256) ((float4*)S)[i] = u4;
    }
    if (tid == 0) {
        mbar_init(mbar_u32, KK);
        mbar_init(mbar_u32 + 8, KK);
    }
    __syncthreads();

    // rows l = k + 10*warp (+80): 13 rows for k<8, 12 for k>=8 (total 128)
    for (int l = k + 10 * warp; l < NN; l += 80) {
        float xi = p_w[l];
        int j4 = lane * 4;
        float s0 = 0.f, s1 = 0.f, s2v = 0.f, s3 = 0.f;
#pragma unroll
        for (int pp = 0; pp < 8; pp++) {
            float4 g = *(const float4*)(g_Gp[pp] + ((size_t)b * NN + l) * NN + j4);
            s0 += g.x; s1 += g.y; s2v += g.z; s3 += g.w;
        }
        float c0 = fmaxf(xi + p_w[j4 + 0] - 2.0f * s0, 0.f);
        float c1 = fmaxf(xi + p_w[j4 + 1] - 2.0f * s1, 0.f);
        float c2 = fmaxf(xi + p_w[j4 + 2] - 2.0f * s2v, 0.f);
        float c3 = fmaxf(xi + p_w[j4 + 3] - 2.0f * s3, 0.f);
        *(float4*)(g_C + ((size_t)b * NN + l) * NN + j4) = make_float4(c0, c1, c2, c3);
        float rs = wsum(c0 + c1 + c2 + c3);
        if (lane == 0) crow[l] = rs;
    }
    __threadfence();       // g_C visible gpu-wide before peers read it
    __syncthreads();
    CLUSTER_SYNC();        // crow slices + mbar init visible cluster-wide

    float a;
    {   // gather full crow via DSMEM, cost0 -> a0
        float v = 0.f;
        if (tid < NN) {
            float cr = dsmem_ld(crow_u32 + (uint32_t)tid * 4u, (uint32_t)r0);
            v = qlq[4 * tid] * cr;
        }
        v = wsum(v);
        if (lane == 0 && warp < 4) cst[warp] = v;
        __syncthreads();
        float cc = (cst[0] + cst[1] + cst[2] + cst[3]) * (1.0f / NN);
        float pen = cc - th;
        a = (pen > 0.f) ? (2.f * RHOc * pen) : 0.f;
        __syncthreads();   // everyone consumed cst before pass-loop reuses it
    }

    // ---------- 30 mirror-ascent iterations ----------
    for (int it = 0; it < NITER; ++it) {
        const bool last = (it == NITER - 1);

        u64 na2 = pk(-a, -a);
        ulonglong2 wva = *(ulonglong2*)&w_s[j0];
        ulonglong2 wvb = *(ulonglong2*)&w_s[j1];
        u64 w2[4] = {wva.x, wva.y, wvb.x, wvb.y};

        u64 pacc2[4] = {0ull, 0ull, 0ull, 0ull};
        u64 cacc2 = 0ull;

#pragma unroll
        for (int pass = 0; pass < 8; ++pass) {
            int l = pass * 16 + warp * 2 + h;
            ulonglong2 qv = *(ulonglong2*)&qlq[4 * l];  // .x=(q,q) .y=(lq,lq)
            u64 ql2 = qv.x, lq2 = qv.y;
            ulonglong2 cva = *(const ulonglong2*)(Cb + l * NN + j0);
            ulonglong2 cvb = *(const ulonglong2*)(Cb + l * NN + j1);
            u64 c2[4] = {cva.x, cva.y, cvb.x, cvb.y};
            ulonglong2 sva = *(ulonglong2*)&S[l * NN + j0];
            ulonglong2 svb = *(ulonglong2*)&S[l * NN + j1];
            u64 s2[4] = {sva.x, sva.y, svb.x, svb.y};

            u64 G2[4], msp = 0ull;
#pragma unroll
            for (int i = 0; i < 4; i++) {
                G2[i] = fma2(na2, c2[i], w2[i]);
                msp = fma2(s2[i], G2[i], msp);
            }
            float mlo, mhi;
            upk(mlo, mhi, msp);
            float ms = hsum16(mlo + mhi);
            u64 nms2 = pk(-ms, -ms);

            u64 d2[4];
#pragma unroll
            for (int i = 0; i < 4; i++)
                d2[i] = mul2(lq2, mul2(s2[i], add2(G2[i], nms2)));

            float d[8];
            upk(d[0], d[1], d2[0]);
            upk(d[2], d[3], d2[1]);
            upk(d[4], d[5], d2[2]);
            upk(d[6], d[7], d2[3]);
            float M = fmaxf(fmaxf(fmaxf(d[0], d[1]), fmaxf(d[2], d[3])),
                            fmaxf(fmaxf(d[4], d[5]), fmaxf(d[6], d[7])));
            M = hmax16(M);

            float x[8];
#pragma unroll
            for (int i = 0; i < 8; i++) x[i] = ex2(d[i] - M);
            u64 x2[4] = {pk(x[0], x[1]), pk(x[2], x[3]),
                         pk(x[4], x[5]), pk(x[6], x[7])};

            u64 e2[4], rp = 0ull;
#pragma unroll
            for (int i = 0; i < 4; i++) {
                e2[i] = mul2(s2[i], x2[i]);
                rp = add2(rp, e2[i]);
            }
            float rlo, rhi;
            upk(rlo, rhi, rp);
            float r = hsum16(rlo + rhi);
            float ir = rcpa(r);
            u64 ir2 = pk(ir, ir);

            u64 cdp = 0ull;
#pragma unroll
            for (int i = 0; i < 4; i++) {
                s2[i] = mul2(e2[i], ir2);
                pacc2[i] = fma2(ql2, s2[i], pacc2[i]);
                cdp = fma2(s2[i], c2[i], cdp);
            }
            cacc2 = fma2(ql2, cdp, cacc2);

            if (!last) {
                *(ulonglong2*)&S[l * NN + j0] = make_ulonglong2(s2[0], s2[1]);
                *(ulonglong2*)&S[l * NN + j1] = make_ulonglong2(s2[2], s2[3]);
            }
        }

        // combine p across the two half-lanes
#pragma unroll
        for (int i = 0; i < 4; i++) {
            u64 o = __shfl_xor_sync(0xffffffffu, pacc2[i], 16);
            pacc2[i] = add2(pacc2[i], o);
        }
        if (h == 0) {
            *(ulonglong2*)&p_w[warp * NN + j0] = make_ulonglong2(pacc2[0], pacc2[1]);
            *(ulonglong2*)&p_w[warp * NN + j1] = make_ulonglong2(pacc2[2], pacc2[3]);
        }
        float clo, chi;
        upk(clo, chi, cacc2);
        float cacc = wsum(clo + chi);
        if (lane == 0) cst[warp] = cacc;
        __syncthreads();

        float pj = 0.f;
        if (tid < NN) {
#pragma unroll
            for (int w2i = 0; w2i < 8; w2i++) pj += p_w[w2i * NN + tid];
        }

        if (last) {
            if (tid < NN) p_out[bk * NN + tid] = pj;
            CLUSTER_SYNC();   // keep smem alive for peers' final DSMEM reads
            return;
        }

        int buf = it & 1;
        if (tid < NN) pb[buf * NN + tid] = pj;
        if (tid == 0) {
            float cc = cst[0] + cst[1] + cst[2] + cst[3] +
                       cst[4] + cst[5] + cst[6] + cst[7];
            float pen = cc - th;
            sm[SM_A] = (pen > 0.f) ? (2.f * RHOc * pen) : 0.f;
        }
        __syncthreads();                       // pb + a visible CTA-wide
        if (tid < KK) mbar_arrive_rank(mbar_u32 + buf * 8, (uint32_t)tid);
        mbar_wait(mbar_u32 + buf * 8, (uint32_t)((it >> 1) & 1));

        a = sm[SM_A];
        if (tid < 64) {        // 2 columns per thread via v2 DSMEM loads
            uint32_t addr = pb_u32 + (uint32_t)(buf * NN + tid * 2) * 4u;
            float p0[KK], p1[KK];
#pragma unroll
            for (int kk = 0; kk < KK; kk++)
                dsmem_ld2(p0[kk], p1[kk], addr, (uint32_t)kk);
            float mn0 = 3.402823466e38f, mn1 = 3.402823466e38f;
#pragma unroll
            for (int kk = 0; kk < KK; kk++) {
                mn0 = fminf(mn0, p0[kk]);
                mn1 = fminf(mn1, p1[kk]);
            }
            float c0 = 0.f, c1 = 0.f;
#pragma unroll
            for (int kk = 0; kk < KK; kk++) {
                c0 += (p0[kk] == mn0) ? 1.f : 0.f;
                c1 += (p1[kk] == mn1) ? 1.f : 0.f;
            }
            w_s[tid * 2]     = (p0[k] == mn0) ? (1.f / c0) : 0.f;
            w_s[tid * 2 + 1] = (p1[k] == mn1) ? (1.f / c1) : 0.f;
        }
        __syncthreads();
    }
}

extern "C" void kernel_launch(void* const* d_in, const int* in_sizes, int n_in,
                              void* d_out, int out_size) {
    const float* X     = (const float*)d_in[0];  // [32,128,512]
    const float* Qp    = (const float*)d_in[1];  // [32,10,128]
    const float* theta = (const float*)d_in[2];  // [32,10]
    float* out = (float*)d_out;                  // [32,10,128]

    cudaFuncSetAttribute(solve_kernel,
                         cudaFuncAttributeMaxDynamicSharedMemorySize, SMEM_BYTES);
    cudaFuncSetAttribute(solve_kernel,
                         cudaFuncAttributeNonPortableClusterSizeAllowed, 1);

    proA_kernel<<<256, 256>>>(X);
    solve_kernel<<<dim3(KK, BB), 256, SMEM_BYTES>>>(Qp, theta, out);
}

// round 15
// speedup vs baseline: 1.1095x; 1.1095x over previous
#include <cuda_runtime.h>
#include <cstdint>

#define BB 32
#define KK 10
#define NN 128
#define FF 512
#define NITER 30
#define LRc 0.5f
#define RHOc 10.0f
#define LOG2E 1.4426950408889634f

typedef unsigned long long u64;

// ---- scratch (static device globals: allocation-free) ----
static __device__ float g_Gp[4][BB * NN * NN];   // 8 MB: four K-quarters of X X^T
static __device__ float g_C[BB * NN * NN];       // 2 MB cost matrix

__device__ __forceinline__ float wsum(float v) {
#pragma unroll
    for (int o = 16; o; o >>= 1) v += __shfl_xor_sync(0xffffffffu, v, o);
    return v;
}
__device__ __forceinline__ float hsum16(float v) {
#pragma unroll
    for (int o = 8; o; o >>= 1) v += __shfl_xor_sync(0xffffffffu, v, o);
    return v;
}
__device__ __forceinline__ float hmax16(float v) {
#pragma unroll
    for (int o = 8; o; o >>= 1) v = fmaxf(v, __shfl_xor_sync(0xffffffffu, v, o));
    return v;
}
__device__ __forceinline__ float ex2(float x) {
    float r;
    asm("ex2.approx.f32 %0, %1;" : "=f"(r) : "f"(x));
    return r;
}
__device__ __forceinline__ float rcpa(float x) {
    float r;
    asm("rcp.approx.f32 %0, %1;" : "=f"(r) : "f"(x));
    return r;
}
// ---- packed f32x2 ----
__device__ __forceinline__ u64 pk(float lo, float hi) {
    u64 r;
    asm("mov.b64 %0, {%1, %2};" : "=l"(r) : "f"(lo), "f"(hi));
    return r;
}
__device__ __forceinline__ void upk(float& lo, float& hi, u64 v) {
    asm("mov.b64 {%0, %1}, %2;" : "=f"(lo), "=f"(hi) : "l"(v));
}
__device__ __forceinline__ u64 fma2(u64 a, u64 b, u64 c) {
    u64 d;
    asm("fma.rn.f32x2 %0, %1, %2, %3;" : "=l"(d) : "l"(a), "l"(b), "l"(c));
    return d;
}
__device__ __forceinline__ u64 mul2(u64 a, u64 b) {
    u64 d;
    asm("mul.rn.f32x2 %0, %1, %2;" : "=l"(d) : "l"(a), "l"(b));
    return d;
}
__device__ __forceinline__ u64 add2(u64 a, u64 b) {
    u64 d;
    asm("add.rn.f32x2 %0, %1, %2;" : "=l"(d) : "l"(a), "l"(b));
    return d;
}
__device__ __forceinline__ uint32_t smem_u32(const void* p) {
    uint32_t a;
    asm("{ .reg .u64 t; cvta.to.shared.u64 t, %1; cvt.u32.u64 %0, t; }"
        : "=r"(a) : "l"(p));
    return a;
}
// mapa is pure address translation -> non-volatile (hoistable/CSE-able)
__device__ __forceinline__ float dsmem_ld(uint32_t addr, uint32_t rank) {
    uint32_t ra; float v;
    asm("mapa.shared::cluster.u32 %0, %1, %2;" : "=r"(ra) : "r"(addr), "r"(rank));
    asm volatile("ld.shared::cluster.f32 %0, [%1];" : "=f"(v) : "r"(ra));
    return v;
}
__device__ __forceinline__ void mbar_init(uint32_t mbar, uint32_t count) {
    asm volatile("mbarrier.init.shared.b64 [%0], %1;" :: "r"(mbar), "r"(count) : "memory");
}
__device__ __forceinline__ void mbar_arrive_rank(uint32_t mbar, uint32_t rank) {
    asm volatile(
        "{ .reg .b32 ra; mapa.shared::cluster.u32 ra, %0, %1;\n\t"
        "mbarrier.arrive.release.cluster.shared::cluster.b64 _, [ra]; }"
        :: "r"(mbar), "r"(rank) : "memory");
}
__device__ __forceinline__ void mbar_wait(uint32_t mbar, uint32_t parity) {
    asm volatile(
        "{ .reg .pred P;\n\t"
        "WL_%=:\n\t"
        "mbarrier.try_wait.parity.acquire.cluster.shared::cta.b64 P, [%0], %1, 0x989680;\n\t"
        "@P bra.uni WD_%=;\n\t"
        "bra.uni WL_%=;\n\t"
        "WD_%=: }"
        :: "r"(mbar), "r"(parity) : "memory");
}
#define CLUSTER_SYNC() do { \
    asm volatile("barrier.cluster.arrive.aligned;" ::: "memory"); \
    asm volatile("barrier.cluster.wait.aligned;" ::: "memory"); } while (0)

// ===== prologue A: G = X X^T, 128x128 single-tile per (b, K-quarter) =====
__global__ void __launch_bounds__(256) proA_kernel(const float* __restrict__ X) {
    int b = blockIdx.x >> 2, ks = blockIdx.x & 3;
    __shared__ float As[16][NN];      // 8 KB; A tile == B tile (G = X X^T)
    const float* Xb = X + (size_t)b * NN * FF;
    int t = threadIdx.x;
    int tx = t & 15, ty = t >> 4;
    int row = t & 127, cq = t >> 7;   // loader mapping
    float acc[8][8];
#pragma unroll
    for (int i = 0; i < 8; i++)
#pragma unroll
        for (int j = 0; j < 8; j++) acc[i][j] = 0.f;

    for (int kc = ks * 128; kc < ks * 128 + 128; kc += 16) {
        float4 v0 = *(const float4*)(Xb + (size_t)row * FF + kc + cq * 8);
        float4 v1 = *(const float4*)(Xb + (size_t)row * FF + kc + cq * 8 + 4);
        if (kc != ks * 128) __syncthreads();
        As[cq * 8 + 0][row] = v0.x; As[cq * 8 + 1][row] = v0.y;
        As[cq * 8 + 2][row] = v0.z; As[cq * 8 + 3][row] = v0.w;
        As[cq * 8 + 4][row] = v1.x; As[cq * 8 + 5][row] = v1.y;
        As[cq * 8 + 6][row] = v1.z; As[cq * 8 + 7][row] = v1.w;
        __syncthreads();
#pragma unroll
        for (int kk = 0; kk < 16; kk++) {
            float4 a0 = *(const float4*)&As[kk][ty * 8];
            float4 a1 = *(const float4*)&As[kk][ty * 8 + 4];
            float4 b0 = *(const float4*)&As[kk][tx * 8];
            float4 b1 = *(const float4*)&As[kk][tx * 8 + 4];
            float av[8] = {a0.x, a0.y, a0.z, a0.w, a1.x, a1.y, a1.z, a1.w};
            float bv[8] = {b0.x, b0.y, b0.z, b0.w, b1.x, b1.y, b1.z, b1.w};
#pragma unroll
            for (int i = 0; i < 8; i++)
#pragma unroll
                for (int j = 0; j < 8; j++)
                    acc[i][j] = fmaf(av[i], bv[j], acc[i][j]);
        }
    }
#pragma unroll
    for (int i = 0; i < 8; i++) {
        float* orow = g_Gp[ks] + ((size_t)b * NN + ty * 8 + i) * NN + tx * 8;
        *(float4*)orow       = make_float4(acc[i][0], acc[i][1], acc[i][2], acc[i][3]);
        *(float4*)(orow + 4) = make_float4(acc[i][4], acc[i][5], acc[i][6], acc[i][7]);
    }
}

// ===== persistent cluster solver: PDL-overlapped init, C build, 30 iterations =====
#define SM_S     0
#define SM_W     16384   /* 128 */
#define SM_QLQ   16512   /* 512: float4 (q,q,lq,lq) per row; 16B aligned */
#define SM_PW    17024   /* 1024 warp partials; phase0: diag(G) in [0..127] */
#define SM_PB    18048   /* 256 double-buffered p row */
#define SM_CROW  18304   /* 128 crow slice (phase 0 exchange) */
#define SM_CST   18432   /* 8 */
#define SM_A     18440   /* 1 */
#define SM_MBAR  18442   /* 16B, 8-aligned (18442*4 % 8 == 0) */
#define SM_FLOATS 18446
#define SMEM_BYTES (SM_FLOATS * 4)

__global__ void __cluster_dims__(KK, 1, 1) __launch_bounds__(256, 3)
solve_kernel(const float* __restrict__ Q, const float* __restrict__ theta,
             float* __restrict__ p_out) {
    extern __shared__ float sm[];
    float* S    = sm + SM_S;
    float* w_s  = sm + SM_W;
    float* qlq  = sm + SM_QLQ;
    float* p_w  = sm + SM_PW;
    float* pb   = sm + SM_PB;
    float* crow = sm + SM_CROW;
    float* cst  = sm + SM_CST;

    int k = blockIdx.x, b = blockIdx.y;
    int bk = b * KK + k;
    int tid = threadIdx.x;
    int warp = tid >> 5, lane = tid & 31;
    int h = lane >> 4, hl = lane & 15;
    int j0 = hl * 4, j1 = 64 + hl * 4;
    int r0 = tid % KK;                       // scalar rotation for crow gather only

    const float* Cb = g_C + (size_t)b * NN * NN;
    const float* G0 = g_Gp[0] + (size_t)b * NN * NN;
    const float* G1 = g_Gp[1] + (size_t)b * NN * NN;
    const float* G2p = g_Gp[2] + (size_t)b * NN * NN;
    const float* G3 = g_Gp[3] + (size_t)b * NN * NN;
    uint32_t pb_u32 = smem_u32(pb);
    uint32_t crow_u32 = smem_u32(crow);
    uint32_t mbar_u32 = smem_u32(sm + SM_MBAR);
    float th = theta[bk];

    // ---------- phase 0a: proA-independent init (overlaps proA via PDL) ----------
    if (tid < NN) {
        float ql = Q[bk * NN + tid];
        float lq = (LRc * LOG2E) * ql;
        *(float4*)&qlq[4 * tid] = make_float4(ql, ql, lq, lq);
        w_s[tid] = 0.f;                      // iter 0: constant w cancels
    }
    {   // S preinit to 1/128 (64 KB of smem stores — the expensive init)
        float4 u4 = make_float4(0.0078125f, 0.0078125f, 0.0078125f, 0.0078125f);
        for (int i = tid; i < NN * NN / 4; i += 256) ((float4*)S)[i] = u4;
    }
    if (tid == 0) {
        mbar_init(mbar_u32, KK);
        mbar_init(mbar_u32 + 8, KK);
    }

    // ---------- PDL: wait for proA's g_Gp to be complete & visible ----------
    cudaGridDependencySynchronize();

    // ---------- phase 0b: diag(G), C rows, a0 ----------
    if (tid < NN) {
        // xn_j == G_jj (diag of full Gram); dgv == 0 exactly -> dropped
        p_w[tid] = G0[tid * NN + tid] + G1[tid * NN + tid] +
                   G2p[tid * NN + tid] + G3[tid * NN + tid];
    }
    __syncthreads();

    // rows l = k + 10*warp (+80): 13 rows for k<8, 12 for k>=8 (total 128)
    for (int l = k + 10 * warp; l < NN; l += 80) {
        float xi = p_w[l];
        int j4 = lane * 4;
        float4 ga = *(const float4*)(G0 + l * NN + j4);
        float4 gb = *(const float4*)(G1 + l * NN + j4);
        float4 gc = *(const float4*)(G2p + l * NN + j4);
        float4 gd4 = *(const float4*)(G3 + l * NN + j4);
        float s0 = ga.x + gb.x + gc.x + gd4.x;
        float s1 = ga.y + gb.y + gc.y + gd4.y;
        float s2v = ga.z + gb.z + gc.z + gd4.z;
        float s3 = ga.w + gb.w + gc.w + gd4.w;
        float c0 = fmaxf(xi + p_w[j4 + 0] - 2.0f * s0, 0.f);
        float c1 = fmaxf(xi + p_w[j4 + 1] - 2.0f * s1, 0.f);
        float c2 = fmaxf(xi + p_w[j4 + 2] - 2.0f * s2v, 0.f);
        float c3 = fmaxf(xi + p_w[j4 + 3] - 2.0f * s3, 0.f);
        *(float4*)(g_C + ((size_t)b * NN + l) * NN + j4) = make_float4(c0, c1, c2, c3);
        float rs = wsum(c0 + c1 + c2 + c3);
        if (lane == 0) crow[l] = rs;
    }
    __threadfence();       // g_C visible gpu-wide before peers read it
    __syncthreads();
    CLUSTER_SYNC();        // crow slices + mbar init visible cluster-wide

    float a;
    {   // gather full crow via DSMEM, cost0 -> a0
        float v = 0.f;
        if (tid < NN) {
            float cr = dsmem_ld(crow_u32 + (uint32_t)tid * 4u, (uint32_t)r0);
            v = qlq[4 * tid] * cr;
        }
        v = wsum(v);
        if (lane == 0 && warp < 4) cst[warp] = v;
        __syncthreads();
        float cc = (cst[0] + cst[1] + cst[2] + cst[3]) * (1.0f / NN);
        float pen = cc - th;
        a = (pen > 0.f) ? (2.f * RHOc * pen) : 0.f;
        __syncthreads();   // everyone consumed cst before pass-loop reuses it
    }

    // ---------- 30 mirror-ascent iterations ----------
    for (int it = 0; it < NITER; ++it) {
        const bool last = (it == NITER - 1);

        u64 na2 = pk(-a, -a);
        ulonglong2 wva = *(ulonglong2*)&w_s[j0];
        ulonglong2 wvb = *(ulonglong2*)&w_s[j1];
        u64 w2[4] = {wva.x, wva.y, wvb.x, wvb.y};

        u64 pacc2[4] = {0ull, 0ull, 0ull, 0ull};
        u64 cacc2 = 0ull;

#pragma unroll
        for (int pass = 0; pass < 8; ++pass) {
            int l = pass * 16 + warp * 2 + h;
            ulonglong2 qv = *(ulonglong2*)&qlq[4 * l];  // .x=(q,q) .y=(lq,lq)
            u64 ql2 = qv.x, lq2 = qv.y;
            ulonglong2 cva = *(const ulonglong2*)(Cb + l * NN + j0);
            ulonglong2 cvb = *(const ulonglong2*)(Cb + l * NN + j1);
            u64 c2[4] = {cva.x, cva.y, cvb.x, cvb.y};
            ulonglong2 sva = *(ulonglong2*)&S[l * NN + j0];
            ulonglong2 svb = *(ulonglong2*)&S[l * NN + j1];
            u64 s2[4] = {sva.x, sva.y, svb.x, svb.y};

            u64 G2[4], msp = 0ull;
#pragma unroll
            for (int i = 0; i < 4; i++) {
                G2[i] = fma2(na2, c2[i], w2[i]);
                msp = fma2(s2[i], G2[i], msp);
            }
            float mlo, mhi;
            upk(mlo, mhi, msp);
            float ms = hsum16(mlo + mhi);
            u64 nms2 = pk(-ms, -ms);

            u64 d2[4];
#pragma unroll
            for (int i = 0; i < 4; i++)
                d2[i] = mul2(lq2, mul2(s2[i], add2(G2[i], nms2)));

            float d[8];
            upk(d[0], d[1], d2[0]);
            upk(d[2], d[3], d2[1]);
            upk(d[4], d[5], d2[2]);
            upk(d[6], d[7], d2[3]);
            float M = fmaxf(fmaxf(fmaxf(d[0], d[1]), fmaxf(d[2], d[3])),
                            fmaxf(fmaxf(d[4], d[5]), fmaxf(d[6], d[7])));
            M = hmax16(M);

            float x[8];
#pragma unroll
            for (int i = 0; i < 8; i++) x[i] = ex2(d[i] - M);
            u64 x2[4] = {pk(x[0], x[1]), pk(x[2], x[3]),
                         pk(x[4], x[5]), pk(x[6], x[7])};

            u64 e2[4], rp = 0ull;
#pragma unroll
            for (int i = 0; i < 4; i++) {
                e2[i] = mul2(s2[i], x2[i]);
                rp = add2(rp, e2[i]);
            }
            float rlo, rhi;
            upk(rlo, rhi, rp);
            float r = hsum16(rlo + rhi);
            float ir = rcpa(r);
            u64 ir2 = pk(ir, ir);

            u64 cdp = 0ull;
#pragma unroll
            for (int i = 0; i < 4; i++) {
                s2[i] = mul2(e2[i], ir2);
                pacc2[i] = fma2(ql2, s2[i], pacc2[i]);
                cdp = fma2(s2[i], c2[i], cdp);
            }
            cacc2 = fma2(ql2, cdp, cacc2);

            if (!last) {
                *(ulonglong2*)&S[l * NN + j0] = make_ulonglong2(s2[0], s2[1]);
                *(ulonglong2*)&S[l * NN + j1] = make_ulonglong2(s2[2], s2[3]);
            }
        }

        // combine p across the two half-lanes
#pragma unroll
        for (int i = 0; i < 4; i++) {
            u64 o = __shfl_xor_sync(0xffffffffu, pacc2[i], 16);
            pacc2[i] = add2(pacc2[i], o);
        }
        if (h == 0) {
            *(ulonglong2*)&p_w[warp * NN + j0] = make_ulonglong2(pacc2[0], pacc2[1]);
            *(ulonglong2*)&p_w[warp * NN + j1] = make_ulonglong2(pacc2[2], pacc2[3]);
        }
        float clo, chi;
        upk(clo, chi, cacc2);
        float cacc = wsum(clo + chi);
        if (lane == 0) cst[warp] = cacc;
        __syncthreads();

        float pj = 0.f;
        if (tid < NN) {
#pragma unroll
            for (int w2i = 0; w2i < 8; w2i++) pj += p_w[w2i * NN + tid];
        }

        if (last) {
            if (tid < NN) p_out[bk * NN + tid] = pj;
            CLUSTER_SYNC();   // keep smem alive for peers' final DSMEM reads
            return;
        }

        int buf = it & 1;
        if (tid < NN) pb[buf * NN + tid] = pj;
        if (tid == 0) {
            float cc = cst[0] + cst[1] + cst[2] + cst[3] +
                       cst[4] + cst[5] + cst[6] + cst[7];
            float pen = cc - th;
            sm[SM_A] = (pen > 0.f) ? (2.f * RHOc * pen) : 0.f;
        }
        __syncthreads();                       // pb + a visible CTA-wide
        if (tid < KK) mbar_arrive_rank(mbar_u32 + buf * 8, (uint32_t)tid);
        mbar_wait(mbar_u32 + buf * 8, (uint32_t)((it >> 1) & 1));

        a = sm[SM_A];
        if (tid < NN) {
            uint32_t addr = pb_u32 + (uint32_t)(buf * NN + tid) * 4u;
            float pv[KK];
            float mn = 3.402823466e38f;
#pragma unroll
            for (int kk = 0; kk < KK; kk++) {       // static indices: stays in registers
                pv[kk] = dsmem_ld(addr, (uint32_t)kk);
                mn = fminf(mn, pv[kk]);
            }
            float cnt2 = 0.f;
#pragma unroll
            for (int kk = 0; kk < KK; kk++) cnt2 += (pv[kk] == mn) ? 1.f : 0.f;
            w_s[tid] = (pv[k] == mn) ? (1.f / cnt2) : 0.f;
        }
        __syncthreads();
    }
}

extern "C" void kernel_launch(void* const* d_in, const int* in_sizes, int n_in,
                              void* d_out, int out_size) {
    const float* X     = (const float*)d_in[0];  // [32,128,512]
    const float* Qp    = (const float*)d_in[1];  // [32,10,128]
    const float* theta = (const float*)d_in[2];  // [32,10]
    float* out = (float*)d_out;                  // [32,10,128]

    cudaFuncSetAttribute(solve_kernel,
                         cudaFuncAttributeMaxDynamicSharedMemorySize, SMEM_BYTES);
    cudaFuncSetAttribute(solve_kernel,
                         cudaFuncAttributeNonPortableClusterSizeAllowed, 1);

    proA_kernel<<<128, 256>>>(X);

    // PDL launch: solve starts while proA runs; cudaGridDependencySynchronize()
    // inside solve gates the g_Gp reads on proA completion.
    cudaLaunchConfig_t cfg = {};
    cfg.gridDim = dim3(KK, BB);
    cfg.blockDim = dim3(256);
    cfg.dynamicSmemBytes = SMEM_BYTES;
    cudaLaunchAttribute attrs[1];
    attrs[0].id = cudaLaunchAttributeProgrammaticStreamSerialization;
    attrs[0].val.programmaticStreamSerializationAllowed = 1;
    cfg.attrs = attrs;
    cfg.numAttrs = 1;
    cudaLaunchKernelEx(&cfg, solve_kernel, Qp, theta, out);
}

// round 16
// speedup vs baseline: 1.1173x; 1.0071x over previous
#include <cuda_runtime.h>
#include <cstdint>

#define BB 32
#define KK 10
#define NN 128
#define FF 512
#define NITER 30
#define LRc 0.5f
#define RHOc 10.0f
#define LOG2E 1.4426950408889634f

typedef unsigned long long u64;

// ---- scratch (static device globals: allocation-free) ----
static __device__ float g_Gp[4][BB * NN * NN];   // 8 MB: four K-quarters of X X^T
static __device__ float g_C[BB * NN * NN];       // 2 MB cost matrix

__device__ __forceinline__ float wsum(float v) {
#pragma unroll
    for (int o = 16; o; o >>= 1) v += __shfl_xor_sync(0xffffffffu, v, o);
    return v;
}
__device__ __forceinline__ float hsum16(float v) {
#pragma unroll
    for (int o = 8; o; o >>= 1) v += __shfl_xor_sync(0xffffffffu, v, o);
    return v;
}
__device__ __forceinline__ float hmax16(float v) {
#pragma unroll
    for (int o = 8; o; o >>= 1) v = fmaxf(v, __shfl_xor_sync(0xffffffffu, v, o));
    return v;
}
__device__ __forceinline__ float ex2(float x) {
    float r;
    asm("ex2.approx.f32 %0, %1;" : "=f"(r) : "f"(x));
    return r;
}
__device__ __forceinline__ float rcpa(float x) {
    float r;
    asm("rcp.approx.f32 %0, %1;" : "=f"(r) : "f"(x));
    return r;
}
// ---- packed f32x2 ----
__device__ __forceinline__ u64 pk(float lo, float hi) {
    u64 r;
    asm("mov.b64 %0, {%1, %2};" : "=l"(r) : "f"(lo), "f"(hi));
    return r;
}
__device__ __forceinline__ void upk(float& lo, float& hi, u64 v) {
    asm("mov.b64 {%0, %1}, %2;" : "=f"(lo), "=f"(hi) : "l"(v));
}
__device__ __forceinline__ u64 fma2(u64 a, u64 b, u64 c) {
    u64 d;
    asm("fma.rn.f32x2 %0, %1, %2, %3;" : "=l"(d) : "l"(a), "l"(b), "l"(c));
    return d;
}
__device__ __forceinline__ u64 mul2(u64 a, u64 b) {
    u64 d;
    asm("mul.rn.f32x2 %0, %1, %2;" : "=l"(d) : "l"(a), "l"(b));
    return d;
}
__device__ __forceinline__ u64 add2(u64 a, u64 b) {
    u64 d;
    asm("add.rn.f32x2 %0, %1, %2;" : "=l"(d) : "l"(a), "l"(b));
    return d;
}
__device__ __forceinline__ uint32_t smem_u32(const void* p) {
    uint32_t a;
    asm("{ .reg .u64 t; cvta.to.shared.u64 t, %1; cvt.u32.u64 %0, t; }"
        : "=r"(a) : "l"(p));
    return a;
}
// mapa is pure address translation -> non-volatile (hoistable/CSE-able)
__device__ __forceinline__ float dsmem_ld(uint32_t addr, uint32_t rank) {
    uint32_t ra; float v;
    asm("mapa.shared::cluster.u32 %0, %1, %2;" : "=r"(ra) : "r"(addr), "r"(rank));
    asm volatile("ld.shared::cluster.f32 %0, [%1];" : "=f"(v) : "r"(ra));
    return v;
}
__device__ __forceinline__ void mbar_init(uint32_t mbar, uint32_t count) {
    asm volatile("mbarrier.init.shared.b64 [%0], %1;" :: "r"(mbar), "r"(count) : "memory");
}
__device__ __forceinline__ void mbar_arrive_rank(uint32_t mbar, uint32_t rank) {
    asm volatile(
        "{ .reg .b32 ra; mapa.shared::cluster.u32 ra, %0, %1;\n\t"
        "mbarrier.arrive.release.cluster.shared::cluster.b64 _, [ra]; }"
        :: "r"(mbar), "r"(rank) : "memory");
}
__device__ __forceinline__ void mbar_wait(uint32_t mbar, uint32_t parity) {
    asm volatile(
        "{ .reg .pred P;\n\t"
        "WL_%=:\n\t"
        "mbarrier.try_wait.parity.acquire.cluster.shared::cta.b64 P, [%0], %1, 0x989680;\n\t"
        "@P bra.uni WD_%=;\n\t"
        "bra.uni WL_%=;\n\t"
        "WD_%=: }"
        :: "r"(mbar), "r"(parity) : "memory");
}
#define CLUSTER_SYNC() do { \
    asm volatile("barrier.cluster.arrive.aligned;" ::: "memory"); \
    asm volatile("barrier.cluster.wait.aligned;" ::: "memory"); } while (0)

// ===== prologue A: G = X X^T via packed f32x2, coalesced tiles =====
// grid 256 = b(32) x ks(4 K-quarters) x cs(2 column halves)
__global__ void __launch_bounds__(256) proA_kernel(const float* __restrict__ X) {
    int b = blockIdx.x >> 3, ks = (blockIdx.x >> 1) & 3, cs = blockIdx.x & 1;
    __shared__ u64 As2[16][NN];       // 16 k-pairs x 128 rows = 16 KB
    const float* Xb = X + (size_t)b * NN * FF;
    int t = threadIdx.x;
    int rg = t >> 4, cg = t & 15;     // out tile: rows rg*8..+7, cols cs*64+cg*4..+3
    int lrow = t >> 1, lhalf = t & 1; // loader: 2 threads per row, 16 consecutive k each

    u64 acc2[8][4];
#pragma unroll
    for (int i = 0; i < 8; i++)
#pragma unroll
        for (int j = 0; j < 4; j++) acc2[i][j] = 0ull;

    for (int kc = ks * 128; kc < ks * 128 + 128; kc += 32) {
        const float* src = Xb + (size_t)lrow * FF + kc + lhalf * 16;
        float4 v0 = *(const float4*)(src);
        float4 v1 = *(const float4*)(src + 4);
        float4 v2 = *(const float4*)(src + 8);
        float4 v3 = *(const float4*)(src + 12);
        if (kc != ks * 128) __syncthreads();
        int kb = lhalf * 8;
        As2[kb + 0][lrow] = pk(v0.x, v0.y); As2[kb + 1][lrow] = pk(v0.z, v0.w);
        As2[kb + 2][lrow] = pk(v1.x, v1.y); As2[kb + 3][lrow] = pk(v1.z, v1.w);
        As2[kb + 4][lrow] = pk(v2.x, v2.y); As2[kb + 5][lrow] = pk(v2.z, v2.w);
        As2[kb + 6][lrow] = pk(v3.x, v3.y); As2[kb + 7][lrow] = pk(v3.z, v3.w);
        __syncthreads();
#pragma unroll
        for (int kp = 0; kp < 16; kp++) {
            ulonglong2 aa0 = *(ulonglong2*)&As2[kp][rg * 8];
            ulonglong2 aa1 = *(ulonglong2*)&As2[kp][rg * 8 + 2];
            ulonglong2 aa2 = *(ulonglong2*)&As2[kp][rg * 8 + 4];
            ulonglong2 aa3 = *(ulonglong2*)&As2[kp][rg * 8 + 6];
            ulonglong2 bb0 = *(ulonglong2*)&As2[kp][cs * 64 + cg * 4];
            ulonglong2 bb1 = *(ulonglong2*)&As2[kp][cs * 64 + cg * 4 + 2];
            u64 a2[8] = {aa0.x, aa0.y, aa1.x, aa1.y, aa2.x, aa2.y, aa3.x, aa3.y};
            u64 b2[4] = {bb0.x, bb0.y, bb1.x, bb1.y};
#pragma unroll
            for (int i = 0; i < 8; i++)
#pragma unroll
                for (int j = 0; j < 4; j++)
                    acc2[i][j] = fma2(a2[i], b2[j], acc2[i][j]);
        }
    }
#pragma unroll
    for (int i = 0; i < 8; i++) {
        float o0, o1, o2, o3, lo, hi;
        upk(lo, hi, acc2[i][0]); o0 = lo + hi;
        upk(lo, hi, acc2[i][1]); o1 = lo + hi;
        upk(lo, hi, acc2[i][2]); o2 = lo + hi;
        upk(lo, hi, acc2[i][3]); o3 = lo + hi;
        float* orow = g_Gp[ks] + ((size_t)b * NN + rg * 8 + i) * NN + cs * 64 + cg * 4;
        *(float4*)orow = make_float4(o0, o1, o2, o3);
    }
}

// ===== persistent cluster solver: PDL-overlapped init, C build, 30 iterations =====
#define SM_S     0
#define SM_W     16384   /* 128 */
#define SM_QLQ   16512   /* 512: float4 (q,q,lq,lq) per row; 16B aligned */
#define SM_PW    17024   /* 1024 warp partials; phase0: diag(G) in [0..127] */
#define SM_PB    18048   /* 256 double-buffered p row */
#define SM_CROW  18304   /* 128 crow slice (phase 0 exchange) */
#define SM_CST   18432   /* 8 */
#define SM_A     18440   /* 1 */
#define SM_MBAR  18442   /* 16B, 8-aligned (18442*4 % 8 == 0) */
#define SM_FLOATS 18446
#define SMEM_BYTES (SM_FLOATS * 4)

__global__ void __cluster_dims__(KK, 1, 1) __launch_bounds__(256, 3)
solve_kernel(const float* __restrict__ Q, const float* __restrict__ theta,
             float* __restrict__ p_out) {
    extern __shared__ float sm[];
    float* S    = sm + SM_S;
    float* w_s  = sm + SM_W;
    float* qlq  = sm + SM_QLQ;
    float* p_w  = sm + SM_PW;
    float* pb   = sm + SM_PB;
    float* crow = sm + SM_CROW;
    float* cst  = sm + SM_CST;

    int k = blockIdx.x, b = blockIdx.y;
    int bk = b * KK + k;
    int tid = threadIdx.x;
    int warp = tid >> 5, lane = tid & 31;
    int h = lane >> 4, hl = lane & 15;
    int j0 = hl * 4, j1 = 64 + hl * 4;
    int r0 = tid % KK;                       // scalar rotation for crow gather only

    const float* Cb = g_C + (size_t)b * NN * NN;
    const float* G0 = g_Gp[0] + (size_t)b * NN * NN;
    const float* G1 = g_Gp[1] + (size_t)b * NN * NN;
    const float* G2p = g_Gp[2] + (size_t)b * NN * NN;
    const float* G3 = g_Gp[3] + (size_t)b * NN * NN;
    uint32_t pb_u32 = smem_u32(pb);
    uint32_t crow_u32 = smem_u32(crow);
    uint32_t mbar_u32 = smem_u32(sm + SM_MBAR);
    float th = theta[bk];

    // ---------- phase 0a: proA-independent init (overlaps proA via PDL) ----------
    if (tid < NN) {
        float ql = Q[bk * NN + tid];
        float lq = (LRc * LOG2E) * ql;
        *(float4*)&qlq[4 * tid] = make_float4(ql, ql, lq, lq);
        w_s[tid] = 0.f;                      // iter 0: constant w cancels
    }
    {   // S preinit to 1/128 (64 KB of smem stores — the expensive init)
        float4 u4 = make_float4(0.0078125f, 0.0078125f, 0.0078125f, 0.0078125f);
        for (int i = tid; i < NN * NN / 4; i += 256) ((float4*)S)[i] = u4;
    }
    if (tid == 0) {
        mbar_init(mbar_u32, KK);
        mbar_init(mbar_u32 + 8, KK);
    }

    // ---------- PDL: wait for proA's g_Gp to be complete & visible ----------
    cudaGridDependencySynchronize();

    // ---------- phase 0b: diag(G), C rows, a0 ----------
    if (tid < NN) {
        // xn_j == G_jj (diag of full Gram); dgv == 0 exactly -> dropped
        p_w[tid] = G0[tid * NN + tid] + G1[tid * NN + tid] +
                   G2p[tid * NN + tid] + G3[tid * NN + tid];
    }
    __syncthreads();

    // rows l = k + 10*warp (+80): 13 rows for k<8, 12 for k>=8 (total 128)
    for (int l = k + 10 * warp; l < NN; l += 80) {
        float xi = p_w[l];
        int j4 = lane * 4;
        float4 ga = *(const float4*)(G0 + l * NN + j4);
        float4 gb = *(const float4*)(G1 + l * NN + j4);
        float4 gc = *(const float4*)(G2p + l * NN + j4);
        float4 gd4 = *(const float4*)(G3 + l * NN + j4);
        float s0 = ga.x + gb.x + gc.x + gd4.x;
        float s1 = ga.y + gb.y + gc.y + gd4.y;
        float s2v = ga.z + gb.z + gc.z + gd4.z;
        float s3 = ga.w + gb.w + gc.w + gd4.w;
        float c0 = fmaxf(xi + p_w[j4 + 0] - 2.0f * s0, 0.f);
        float c1 = fmaxf(xi + p_w[j4 + 1] - 2.0f * s1, 0.f);
        float c2 = fmaxf(xi + p_w[j4 + 2] - 2.0f * s2v, 0.f);
        float c3 = fmaxf(xi + p_w[j4 + 3] - 2.0f * s3, 0.f);
        *(float4*)(g_C + ((size_t)b * NN + l) * NN + j4) = make_float4(c0, c1, c2, c3);
        float rs = wsum(c0 + c1 + c2 + c3);
        if (lane == 0) crow[l] = rs;
    }
    __threadfence();       // g_C visible gpu-wide before peers read it
    __syncthreads();
    CLUSTER_SYNC();        // crow slices + mbar init visible cluster-wide

    float a;
    {   // gather full crow via DSMEM, cost0 -> a0
        float v = 0.f;
        if (tid < NN) {
            float cr = dsmem_ld(crow_u32 + (uint32_t)tid * 4u, (uint32_t)r0);
            v = qlq[4 * tid] * cr;
        }
        v = wsum(v);
        if (lane == 0 && warp < 4) cst[warp] = v;
        __syncthreads();
        float cc = (cst[0] + cst[1] + cst[2] + cst[3]) * (1.0f / NN);
        float pen = cc - th;
        a = (pen > 0.f) ? (2.f * RHOc * pen) : 0.f;
        __syncthreads();   // everyone consumed cst before pass-loop reuses it
    }

    // ---------- 30 mirror-ascent iterations ----------
    for (int it = 0; it < NITER; ++it) {
        const bool last = (it == NITER - 1);

        u64 na2 = pk(-a, -a);
        ulonglong2 wva = *(ulonglong2*)&w_s[j0];
        ulonglong2 wvb = *(ulonglong2*)&w_s[j1];
        u64 w2[4] = {wva.x, wva.y, wvb.x, wvb.y};

        u64 pacc2[4] = {0ull, 0ull, 0ull, 0ull};
        u64 cacc2 = 0ull;

#pragma unroll
        for (int pass = 0; pass < 8; ++pass) {
            int l = pass * 16 + warp * 2 + h;
            ulonglong2 qv = *(ulonglong2*)&qlq[4 * l];  // .x=(q,q) .y=(lq,lq)
            u64 ql2 = qv.x, lq2 = qv.y;
            ulonglong2 cva = *(const ulonglong2*)(Cb + l * NN + j0);
            ulonglong2 cvb = *(const ulonglong2*)(Cb + l * NN + j1);
            u64 c2[4] = {cva.x, cva.y, cvb.x, cvb.y};
            ulonglong2 sva = *(ulonglong2*)&S[l * NN + j0];
            ulonglong2 svb = *(ulonglong2*)&S[l * NN + j1];
            u64 s2[4] = {sva.x, sva.y, svb.x, svb.y};

            u64 G2[4], msp = 0ull;
#pragma unroll
            for (int i = 0; i < 4; i++) {
                G2[i] = fma2(na2, c2[i], w2[i]);
                msp = fma2(s2[i], G2[i], msp);
            }
            float mlo, mhi;
            upk(mlo, mhi, msp);
            float ms = hsum16(mlo + mhi);
            u64 nms2 = pk(-ms, -ms);

            u64 d2[4];
#pragma unroll
            for (int i = 0; i < 4; i++)
                d2[i] = mul2(lq2, mul2(s2[i], add2(G2[i], nms2)));

            float d[8];
            upk(d[0], d[1], d2[0]);
            upk(d[2], d[3], d2[1]);
            upk(d[4], d[5], d2[2]);
            upk(d[6], d[7], d2[3]);
            float M = fmaxf(fmaxf(fmaxf(d[0], d[1]), fmaxf(d[2], d[3])),
                            fmaxf(fmaxf(d[4], d[5]), fmaxf(d[6], d[7])));
            M = hmax16(M);

            float x[8];
#pragma unroll
            for (int i = 0; i < 8; i++) x[i] = ex2(d[i] - M);
            u64 x2[4] = {pk(x[0], x[1]), pk(x[2], x[3]),
                         pk(x[4], x[5]), pk(x[6], x[7])};

            u64 e2[4], rp = 0ull;
#pragma unroll
            for (int i = 0; i < 4; i++) {
                e2[i] = mul2(s2[i], x2[i]);
                rp = add2(rp, e2[i]);
            }
            float rlo, rhi;
            upk(rlo, rhi, rp);
            float r = hsum16(rlo + rhi);
            float ir = rcpa(r);
            u64 ir2 = pk(ir, ir);

            u64 cdp = 0ull;
#pragma unroll
            for (int i = 0; i < 4; i++) {
                s2[i] = mul2(e2[i], ir2);
                pacc2[i] = fma2(ql2, s2[i], pacc2[i]);
                cdp = fma2(s2[i], c2[i], cdp);
            }
            cacc2 = fma2(ql2, cdp, cacc2);

            if (!last) {
                *(ulonglong2*)&S[l * NN + j0] = make_ulonglong2(s2[0], s2[1]);
                *(ulonglong2*)&S[l * NN + j1] = make_ulonglong2(s2[2], s2[3]);
            }
        }

        // combine p across the two half-lanes
#pragma unroll
        for (int i = 0; i < 4; i++) {
            u64 o = __shfl_xor_sync(0xffffffffu, pacc2[i], 16);
            pacc2[i] = add2(pacc2[i], o);
        }
        if (h == 0) {
            *(ulonglong2*)&p_w[warp * NN + j0] = make_ulonglong2(pacc2[0], pacc2[1]);
            *(ulonglong2*)&p_w[warp * NN + j1] = make_ulonglong2(pacc2[2], pacc2[3]);
        }
        float clo, chi;
        upk(clo, chi, cacc2);
        float cacc = wsum(clo + chi);
        if (lane == 0) cst[warp] = cacc;
        __syncthreads();

        float pj = 0.f;
        if (tid < NN) {
#pragma unroll
            for (int w2i = 0; w2i < 8; w2i++) pj += p_w[w2i * NN + tid];
        }

        if (last) {
            if (tid < NN) p_out[bk * NN + tid] = pj;
            CLUSTER_SYNC();   // keep smem alive for peers' final DSMEM reads
            return;
        }

        int buf = it & 1;
        if (tid < NN) pb[buf * NN + tid] = pj;
        if (tid == 0) {
            float cc = cst[0] + cst[1] + cst[2] + cst[3] +
                       cst[4] + cst[5] + cst[6] + cst[7];
            float pen = cc - th;
            sm[SM_A] = (pen > 0.f) ? (2.f * RHOc * pen) : 0.f;
        }
        __syncthreads();                       // pb + a visible CTA-wide
        if (tid < KK) mbar_arrive_rank(mbar_u32 + buf * 8, (uint32_t)tid);
        mbar_wait(mbar_u32 + buf * 8, (uint32_t)((it >> 1) & 1));

        a = sm[SM_A];
        if (tid < NN) {
            uint32_t addr = pb_u32 + (uint32_t)(buf * NN + tid) * 4u;
            float pv[KK];
            float mn = 3.402823466e38f;
#pragma unroll
            for (int kk = 0; kk < KK; kk++) {       // static indices: stays in registers
                pv[kk] = dsmem_ld(addr, (uint32_t)kk);
                mn = fminf(mn, pv[kk]);
            }
            float cnt2 = 0.f;
#pragma unroll
            for (int kk = 0; kk < KK; kk++) cnt2 += (pv[kk] == mn) ? 1.f : 0.f;
            w_s[tid] = (pv[k] == mn) ? (1.f / cnt2) : 0.f;
        }
        __syncthreads();
    }
}

extern "C" void kernel_launch(void* const* d_in, const int* in_sizes, int n_in,
                              void* d_out, int out_size) {
    const float* X     = (const float*)d_in[0];  // [32,128,512]
    const float* Qp    = (const float*)d_in[1];  // [32,10,128]
    const float* theta = (const float*)d_in[2];  // [32,10]
    float* out = (float*)d_out;                  // [32,10,128]

    cudaFuncSetAttribute(solve_kernel,
                         cudaFuncAttributeMaxDynamicSharedMemorySize, SMEM_BYTES);
    cudaFuncSetAttribute(solve_kernel,
                         cudaFuncAttributeNonPortableClusterSizeAllowed, 1);

    proA_kernel<<<256, 256>>>(X);

    // PDL launch: solve starts while proA runs; cudaGridDependencySynchronize()
    // inside solve gates the g_Gp reads on proA completion.
    cudaLaunchConfig_t cfg = {};
    cfg.gridDim = dim3(KK, BB);
    cfg.blockDim = dim3(256);
    cfg.dynamicSmemBytes = SMEM_BYTES;
    cudaLaunchAttribute attrs[1];
    attrs[0].id = cudaLaunchAttributeProgrammaticStreamSerialization;
    attrs[0].val.programmaticStreamSerializationAllowed = 1;
    cfg.attrs = attrs;
    cfg.numAttrs = 1;
    cudaLaunchKernelEx(&cfg, solve_kernel, Qp, theta, out);
}

// round 17
// speedup vs baseline: 1.1384x; 1.0188x over previous
#include <cuda_runtime.h>
#include <cstdint>

#define BB 32
#define KK 10
#define NN 128
#define FF 512
#define NITER 30
#define LRc 0.5f
#define RHOc 10.0f
#define LOG2E 1.4426950408889634f

typedef unsigned long long u64;

// ---- scratch (static device globals: allocation-free) ----
static __device__ float g_Gp[4][BB * NN * NN];   // 8 MB: four K-quarters of X X^T
static __device__ float g_C[BB * NN * NN];       // 2 MB cost matrix

__device__ __forceinline__ float wsum(float v) {
#pragma unroll
    for (int o = 16; o; o >>= 1) v += __shfl_xor_sync(0xffffffffu, v, o);
    return v;
}
__device__ __forceinline__ float hsum16(float v) {
#pragma unroll
    for (int o = 8; o; o >>= 1) v += __shfl_xor_sync(0xffffffffu, v, o);
    return v;
}
__device__ __forceinline__ float hmax16(float v) {
#pragma unroll
    for (int o = 8; o; o >>= 1) v = fmaxf(v, __shfl_xor_sync(0xffffffffu, v, o));
    return v;
}
__device__ __forceinline__ float ex2(float x) {
    float r;
    asm("ex2.approx.f32 %0, %1;" : "=f"(r) : "f"(x));
    return r;
}
__device__ __forceinline__ float rcpa(float x) {
    float r;
    asm("rcp.approx.f32 %0, %1;" : "=f"(r) : "f"(x));
    return r;
}
// ---- packed f32x2 ----
__device__ __forceinline__ u64 pk(float lo, float hi) {
    u64 r;
    asm("mov.b64 %0, {%1, %2};" : "=l"(r) : "f"(lo), "f"(hi));
    return r;
}
__device__ __forceinline__ void upk(float& lo, float& hi, u64 v) {
    asm("mov.b64 {%0, %1}, %2;" : "=f"(lo), "=f"(hi) : "l"(v));
}
__device__ __forceinline__ u64 fma2(u64 a, u64 b, u64 c) {
    u64 d;
    asm("fma.rn.f32x2 %0, %1, %2, %3;" : "=l"(d) : "l"(a), "l"(b), "l"(c));
    return d;
}
__device__ __forceinline__ u64 mul2(u64 a, u64 b) {
    u64 d;
    asm("mul.rn.f32x2 %0, %1, %2;" : "=l"(d) : "l"(a), "l"(b));
    return d;
}
__device__ __forceinline__ u64 add2(u64 a, u64 b) {
    u64 d;
    asm("add.rn.f32x2 %0, %1, %2;" : "=l"(d) : "l"(a), "l"(b));
    return d;
}
__device__ __forceinline__ uint32_t smem_u32(const void* p) {
    uint32_t a;
    asm("{ .reg .u64 t; cvta.to.shared.u64 t, %1; cvt.u32.u64 %0, t; }"
        : "=r"(a) : "l"(p));
    return a;
}
// mapa is pure address translation -> non-volatile (hoistable/CSE-able)
__device__ __forceinline__ float dsmem_ld(uint32_t addr, uint32_t rank) {
    uint32_t ra; float v;
    asm("mapa.shared::cluster.u32 %0, %1, %2;" : "=r"(ra) : "r"(addr), "r"(rank));
    asm volatile("ld.shared::cluster.f32 %0, [%1];" : "=f"(v) : "r"(ra));
    return v;
}
__device__ __forceinline__ void mbar_init(uint32_t mbar, uint32_t count) {
    asm volatile("mbarrier.init.shared.b64 [%0], %1;" :: "r"(mbar), "r"(count) : "memory");
}
__device__ __forceinline__ void mbar_arrive_rank(uint32_t mbar, uint32_t rank) {
    asm volatile(
        "{ .reg .b32 ra; mapa.shared::cluster.u32 ra, %0, %1;\n\t"
        "mbarrier.arrive.release.cluster.shared::cluster.b64 _, [ra]; }"
        :: "r"(mbar), "r"(rank) : "memory");
}
__device__ __forceinline__ void mbar_wait(uint32_t mbar, uint32_t parity) {
    asm volatile(
        "{ .reg .pred P;\n\t"
        "WL_%=:\n\t"
        "mbarrier.try_wait.parity.acquire.cluster.shared::cta.b64 P, [%0], %1, 0x989680;\n\t"
        "@P bra.uni WD_%=;\n\t"
        "bra.uni WL_%=;\n\t"
        "WD_%=: }"
        :: "r"(mbar), "r"(parity) : "memory");
}
#define CLUSTER_SYNC() do { \
    asm volatile("barrier.cluster.arrive.aligned;" ::: "memory"); \
    asm volatile("barrier.cluster.wait.aligned;" ::: "memory"); } while (0)

// ===== prologue A: G = X X^T via packed f32x2, coalesced tiles =====
// grid 256 = b(32) x ks(4 K-quarters) x cs(2 column halves)
__global__ void __launch_bounds__(256) proA_kernel(const float* __restrict__ X) {
    int b = blockIdx.x >> 3, ks = (blockIdx.x >> 1) & 3, cs = blockIdx.x & 1;
    __shared__ u64 As2[16][NN];       // 16 k-pairs x 128 rows = 16 KB
    const float* Xb = X + (size_t)b * NN * FF;
    int t = threadIdx.x;
    int rg = t >> 4, cg = t & 15;     // out tile: rows rg*8..+7, cols cs*64+cg*4..+3
    int lrow = t >> 1, lhalf = t & 1; // loader: 2 threads per row, 16 consecutive k each

    u64 acc2[8][4];
#pragma unroll
    for (int i = 0; i < 8; i++)
#pragma unroll
        for (int j = 0; j < 4; j++) acc2[i][j] = 0ull;

    for (int kc = ks * 128; kc < ks * 128 + 128; kc += 32) {
        const float* src = Xb + (size_t)lrow * FF + kc + lhalf * 16;
        float4 v0 = *(const float4*)(src);
        float4 v1 = *(const float4*)(src + 4);
        float4 v2 = *(const float4*)(src + 8);
        float4 v3 = *(const float4*)(src + 12);
        if (kc != ks * 128) __syncthreads();
        int kb = lhalf * 8;
        As2[kb + 0][lrow] = pk(v0.x, v0.y); As2[kb + 1][lrow] = pk(v0.z, v0.w);
        As2[kb + 2][lrow] = pk(v1.x, v1.y); As2[kb + 3][lrow] = pk(v1.z, v1.w);
        As2[kb + 4][lrow] = pk(v2.x, v2.y); As2[kb + 5][lrow] = pk(v2.z, v2.w);
        As2[kb + 6][lrow] = pk(v3.x, v3.y); As2[kb + 7][lrow] = pk(v3.z, v3.w);
        __syncthreads();
#pragma unroll
        for (int kp = 0; kp < 16; kp++) {
            ulonglong2 aa0 = *(ulonglong2*)&As2[kp][rg * 8];
            ulonglong2 aa1 = *(ulonglong2*)&As2[kp][rg * 8 + 2];
            ulonglong2 aa2 = *(ulonglong2*)&As2[kp][rg * 8 + 4];
            ulonglong2 aa3 = *(ulonglong2*)&As2[kp][rg * 8 + 6];
            ulonglong2 bb0 = *(ulonglong2*)&As2[kp][cs * 64 + cg * 4];
            ulonglong2 bb1 = *(ulonglong2*)&As2[kp][cs * 64 + cg * 4 + 2];
            u64 a2[8] = {aa0.x, aa0.y, aa1.x, aa1.y, aa2.x, aa2.y, aa3.x, aa3.y};
            u64 b2[4] = {bb0.x, bb0.y, bb1.x, bb1.y};
#pragma unroll
            for (int i = 0; i < 8; i++)
#pragma unroll
                for (int j = 0; j < 4; j++)
                    acc2[i][j] = fma2(a2[i], b2[j], acc2[i][j]);
        }
    }
#pragma unroll
    for (int i = 0; i < 8; i++) {
        float o0, o1, o2, o3, lo, hi;
        upk(lo, hi, acc2[i][0]); o0 = lo + hi;
        upk(lo, hi, acc2[i][1]); o1 = lo + hi;
        upk(lo, hi, acc2[i][2]); o2 = lo + hi;
        upk(lo, hi, acc2[i][3]); o3 = lo + hi;
        float* orow = g_Gp[ks] + ((size_t)b * NN + rg * 8 + i) * NN + cs * 64 + cg * 4;
        *(float4*)orow = make_float4(o0, o1, o2, o3);
    }
}

// ===== persistent cluster solver: PDL-overlapped init, C build, 30 iterations =====
#define SM_S     0
#define SM_W     16384   /* 128 */
#define SM_QLQ   16512   /* 512: float4 (q,q,lq,lq) per row; 16B aligned */
#define SM_PW    17024   /* 1024 warp partials; phase0: diag(G) in [0..127] */
#define SM_PB    18048   /* 256 double-buffered p row */
#define SM_CROW  18304   /* 128 crow slice (phase 0 exchange) */
#define SM_CST   18432   /* 8 */
#define SM_A     18440   /* 1 */
#define SM_MBAR  18442   /* 16B, 8-aligned (18442*4 % 8 == 0) */
#define SM_FLOATS 18446
#define SMEM_BYTES (SM_FLOATS * 4)

__global__ void __cluster_dims__(KK, 1, 1) __launch_bounds__(256, 3)
solve_kernel(const float* __restrict__ Q, const float* __restrict__ theta,
             float* __restrict__ p_out) {
    extern __shared__ float sm[];
    float* S    = sm + SM_S;
    float* w_s  = sm + SM_W;
    float* qlq  = sm + SM_QLQ;
    float* p_w  = sm + SM_PW;
    float* pb   = sm + SM_PB;
    float* crow = sm + SM_CROW;
    float* cst  = sm + SM_CST;

    int k = blockIdx.x, b = blockIdx.y;
    int bk = b * KK + k;
    int tid = threadIdx.x;
    int warp = tid >> 5, lane = tid & 31;
    int h = lane >> 4, hl = lane & 15;
    int j0 = hl * 4, j1 = 64 + hl * 4;
    int r0 = tid % KK;                       // scalar rotation for crow gather only

    const float* Cb = g_C + (size_t)b * NN * NN;
    const float* G0 = g_Gp[0] + (size_t)b * NN * NN;
    const float* G1 = g_Gp[1] + (size_t)b * NN * NN;
    const float* G2p = g_Gp[2] + (size_t)b * NN * NN;
    const float* G3 = g_Gp[3] + (size_t)b * NN * NN;
    uint32_t pb_u32 = smem_u32(pb);
    uint32_t crow_u32 = smem_u32(crow);
    uint32_t mbar_u32 = smem_u32(sm + SM_MBAR);
    float th = theta[bk];

    // ---------- phase 0a: proA-independent init (overlaps proA via PDL) ----------
    if (tid < NN) {
        float ql = Q[bk * NN + tid];
        float lq = (LRc * LOG2E) * ql;
        *(float4*)&qlq[4 * tid] = make_float4(ql, ql, lq, lq);
        w_s[tid] = 0.f;                      // iter 0: constant w cancels
    }
    {   // S preinit to 1/128 (64 KB of smem stores — the expensive init)
        float4 u4 = make_float4(0.0078125f, 0.0078125f, 0.0078125f, 0.0078125f);
        for (int i = tid; i < NN * NN / 4; i += 256) ((float4*)S)[i] = u4;
    }
    if (tid == 0) {
        mbar_init(mbar_u32, KK);
        mbar_init(mbar_u32 + 8, KK);
    }

    // ---------- PDL: wait for proA's g_Gp to be complete & visible ----------
    cudaGridDependencySynchronize();

    // ---------- phase 0b: diag(G), C rows, a0 ----------
    if (tid < NN) {
        // xn_j == G_jj (diag of full Gram); dgv == 0 exactly -> dropped
        p_w[tid] = G0[tid * NN + tid] + G1[tid * NN + tid] +
                   G2p[tid * NN + tid] + G3[tid * NN + tid];
    }
    __syncthreads();

    // rows l = k + 10*warp (+80): 13 rows for k<8, 12 for k>=8 (total 128)
    for (int l = k + 10 * warp; l < NN; l += 80) {
        float xi = p_w[l];
        int j4 = lane * 4;
        float4 ga = *(const float4*)(G0 + l * NN + j4);
        float4 gb = *(const float4*)(G1 + l * NN + j4);
        float4 gc = *(const float4*)(G2p + l * NN + j4);
        float4 gd4 = *(const float4*)(G3 + l * NN + j4);
        float s0 = ga.x + gb.x + gc.x + gd4.x;
        float s1 = ga.y + gb.y + gc.y + gd4.y;
        float s2v = ga.z + gb.z + gc.z + gd4.z;
        float s3 = ga.w + gb.w + gc.w + gd4.w;
        float c0 = fmaxf(xi + p_w[j4 + 0] - 2.0f * s0, 0.f);
        float c1 = fmaxf(xi + p_w[j4 + 1] - 2.0f * s1, 0.f);
        float c2 = fmaxf(xi + p_w[j4 + 2] - 2.0f * s2v, 0.f);
        float c3 = fmaxf(xi + p_w[j4 + 3] - 2.0f * s3, 0.f);
        *(float4*)(g_C + ((size_t)b * NN + l) * NN + j4) = make_float4(c0, c1, c2, c3);
        float rs = wsum(c0 + c1 + c2 + c3);
        if (lane == 0) crow[l] = rs;
    }
    __threadfence();       // g_C visible gpu-wide before peers read it
    __syncthreads();
    CLUSTER_SYNC();        // crow slices + mbar init visible cluster-wide

    float a;
    {   // gather full crow via DSMEM, cost0 -> a0
        float v = 0.f;
        if (tid < NN) {
            float cr = dsmem_ld(crow_u32 + (uint32_t)tid * 4u, (uint32_t)r0);
            v = qlq[4 * tid] * cr;
        }
        v = wsum(v);
        if (lane == 0 && warp < 4) cst[warp] = v;
        __syncthreads();
        float cc = (cst[0] + cst[1] + cst[2] + cst[3]) * (1.0f / NN);
        float pen = cc - th;
        a = (pen > 0.f) ? (2.f * RHOc * pen) : 0.f;
        __syncthreads();   // everyone consumed cst before pass-loop reuses it
    }

    // C prefetch buffer for pass 0 (rows are iteration-invariant)
    int lp0 = warp * 2 + h;
    u64 c2[4];
    {
        ulonglong2 cva = *(const ulonglong2*)(Cb + lp0 * NN + j0);
        ulonglong2 cvb = *(const ulonglong2*)(Cb + lp0 * NN + j1);
        c2[0] = cva.x; c2[1] = cva.y; c2[2] = cvb.x; c2[3] = cvb.y;
    }

    // ---------- 30 mirror-ascent iterations ----------
    for (int it = 0; it < NITER; ++it) {
        const bool last = (it == NITER - 1);

        u64 na2 = pk(-a, -a);
        ulonglong2 wva = *(ulonglong2*)&w_s[j0];
        ulonglong2 wvb = *(ulonglong2*)&w_s[j1];
        u64 w2[4] = {wva.x, wva.y, wvb.x, wvb.y};

        u64 pacc2[4] = {0ull, 0ull, 0ull, 0ull};
        u64 cacc2 = 0ull;

#pragma unroll
        for (int pass = 0; pass < 8; ++pass) {
            int l = pass * 16 + warp * 2 + h;
            ulonglong2 qv = *(ulonglong2*)&qlq[4 * l];  // .x=(q,q) .y=(lq,lq)
            u64 ql2 = qv.x, lq2 = qv.y;
            ulonglong2 sva = *(ulonglong2*)&S[l * NN + j0];
            ulonglong2 svb = *(ulonglong2*)&S[l * NN + j1];
            u64 s2[4] = {sva.x, sva.y, svb.x, svb.y};

            u64 G2[4], msp = 0ull;
#pragma unroll
            for (int i = 0; i < 4; i++) {
                G2[i] = fma2(na2, c2[i], w2[i]);
                msp = fma2(s2[i], G2[i], msp);
            }
            float mlo, mhi;
            upk(mlo, mhi, msp);
            float ms = hsum16(mlo + mhi);
            u64 nms2 = pk(-ms, -ms);

            u64 d2[4];
#pragma unroll
            for (int i = 0; i < 4; i++)
                d2[i] = mul2(lq2, mul2(s2[i], add2(G2[i], nms2)));

            float d[8];
            upk(d[0], d[1], d2[0]);
            upk(d[2], d[3], d2[1]);
            upk(d[4], d[5], d2[2]);
            upk(d[6], d[7], d2[3]);
            float M = fmaxf(fmaxf(fmaxf(d[0], d[1]), fmaxf(d[2], d[3])),
                            fmaxf(fmaxf(d[4], d[5]), fmaxf(d[6], d[7])));
            M = hmax16(M);

            float x[8];
#pragma unroll
            for (int i = 0; i < 8; i++) x[i] = ex2(d[i] - M);
            u64 x2[4] = {pk(x[0], x[1]), pk(x[2], x[3]),
                         pk(x[4], x[5]), pk(x[6], x[7])};

            // e2, r, and cost-dot on UN-normalized e2 -> c2 dead after this block
            u64 e2[4], rp = 0ull, cdr = 0ull;
#pragma unroll
            for (int i = 0; i < 4; i++) {
                e2[i] = mul2(s2[i], x2[i]);
                rp = add2(rp, e2[i]);
                cdr = fma2(e2[i], c2[i], cdr);
            }

            // PREFETCH next pass's C rows now (covers r-reduce + tail; pass 7
            // prefetches pass 0, covering the whole exchange at iter boundary)
            {
                int ln = (pass < 7) ? (l + 16) : lp0;
                ulonglong2 cva = *(const ulonglong2*)(Cb + ln * NN + j0);
                ulonglong2 cvb = *(const ulonglong2*)(Cb + ln * NN + j1);
                c2[0] = cva.x; c2[1] = cva.y; c2[2] = cvb.x; c2[3] = cvb.y;
            }

            float rlo, rhi;
            upk(rlo, rhi, rp);
            float r = hsum16(rlo + rhi);
            float ir = rcpa(r);
            u64 ir2 = pk(ir, ir);

#pragma unroll
            for (int i = 0; i < 4; i++) {
                s2[i] = mul2(e2[i], ir2);
                pacc2[i] = fma2(ql2, s2[i], pacc2[i]);
            }
            cacc2 = fma2(mul2(ql2, ir2), cdr, cacc2);

            if (!last) {
                *(ulonglong2*)&S[l * NN + j0] = make_ulonglong2(s2[0], s2[1]);
                *(ulonglong2*)&S[l * NN + j1] = make_ulonglong2(s2[2], s2[3]);
            }
        }

        // combine p across the two half-lanes
#pragma unroll
        for (int i = 0; i < 4; i++) {
            u64 o = __shfl_xor_sync(0xffffffffu, pacc2[i], 16);
            pacc2[i] = add2(pacc2[i], o);
        }
        if (h == 0) {
            *(ulonglong2*)&p_w[warp * NN + j0] = make_ulonglong2(pacc2[0], pacc2[1]);
            *(ulonglong2*)&p_w[warp * NN + j1] = make_ulonglong2(pacc2[2], pacc2[3]);
        }
        float clo, chi;
        upk(clo, chi, cacc2);
        float cacc = wsum(clo + chi);
        if (lane == 0) cst[warp] = cacc;
        __syncthreads();

        float pj = 0.f;
        if (tid < NN) {
#pragma unroll
            for (int w2i = 0; w2i < 8; w2i++) pj += p_w[w2i * NN + tid];
        }

        if (last) {
            if (tid < NN) p_out[bk * NN + tid] = pj;
            CLUSTER_SYNC();   // keep smem alive for peers' final DSMEM reads
            return;
        }

        int buf = it & 1;
        if (tid < NN) pb[buf * NN + tid] = pj;
        if (tid == 0) {
            float cc = cst[0] + cst[1] + cst[2] + cst[3] +
                       cst[4] + cst[5] + cst[6] + cst[7];
            float pen = cc - th;
            sm[SM_A] = (pen > 0.f) ? (2.f * RHOc * pen) : 0.f;
        }
        __syncthreads();                       // pb + a visible CTA-wide
        if (tid < KK) mbar_arrive_rank(mbar_u32 + buf * 8, (uint32_t)tid);
        mbar_wait(mbar_u32 + buf * 8, (uint32_t)((it >> 1) & 1));

        a = sm[SM_A];
        if (tid < NN) {
            uint32_t addr = pb_u32 + (uint32_t)(buf * NN + tid) * 4u;
            float pv[KK];
            float mn = 3.402823466e38f;
#pragma unroll
            for (int kk = 0; kk < KK; kk++) {       // static indices: stays in registers
                pv[kk] = dsmem_ld(addr, (uint32_t)kk);
                mn = fminf(mn, pv[kk]);
            }
            float cnt2 = 0.f;
#pragma unroll
            for (int kk = 0; kk < KK; kk++) cnt2 += (pv[kk] == mn) ? 1.f : 0.f;
            w_s[tid] = (pv[k] == mn) ? (1.f / cnt2) : 0.f;
        }
        __syncthreads();
    }
}

extern "C" void kernel_launch(void* const* d_in, const int* in_sizes, int n_in,
                              void* d_out, int out_size) {
    const float* X     = (const float*)d_in[0];  // [32,128,512]
    const float* Qp    = (const float*)d_in[1];  // [32,10,128]
    const float* theta = (const float*)d_in[2];  // [32,10]
    float* out = (float*)d_out;                  // [32,10,128]

    cudaFuncSetAttribute(solve_kernel,
                         cudaFuncAttributeMaxDynamicSharedMemorySize, SMEM_BYTES);
    cudaFuncSetAttribute(solve_kernel,
                         cudaFuncAttributeNonPortableClusterSizeAllowed, 1);

    proA_kernel<<<256, 256>>>(X);

    // PDL launch: solve starts while proA runs; cudaGridDependencySynchronize()
    // inside solve gates the g_Gp reads on proA completion.
    cudaLaunchConfig_t cfg = {};
    cfg.gridDim = dim3(KK, BB);
    cfg.blockDim = dim3(256);
    cfg.dynamicSmemBytes = SMEM_BYTES;
    cudaLaunchAttribute attrs[1];
    attrs[0].id = cudaLaunchAttributeProgrammaticStreamSerialization;
    attrs[0].val.programmaticStreamSerializationAllowed = 1;
    cfg.attrs = attrs;
    cfg.numAttrs = 1;
    cudaLaunchKernelEx(&cfg, solve_kernel, Qp, theta, out);
}